// round 2
// baseline (speedup 1.0000x reference)
#include <cuda_runtime.h>

#define EPS 1e-5f

// ---------------- scratch (device globals; no allocations) ----------------
__device__ float g_x[4 * 16 * 128 * 128];     // conv3x3+bn+prelu output, 4 MB
__device__ float g_q[4 * 128 * 4096];         // Q  [b][c][n], 8 MB
__device__ float g_k[4 * 128 * 4096];         // K
__device__ float g_v[4 * 128 * 4096];         // V

// ============================================================================
// Kernel 1: conv3x3 (64->16) + BN + PReLU at 128x128
// grid (8,8,4): 16x16 spatial tile, all 16 oc per block. 256 threads.
// thread = (oc = t&15, 4x4 pixel patch = t>>4)
// ============================================================================
__global__ __launch_bounds__(256) void conv3_kernel(
    const float* __restrict__ em, const float* __restrict__ en_w,
    const float* __restrict__ en_b,
    const float* __restrict__ bn1_g, const float* __restrict__ bn1_b,
    const float* __restrict__ bn1_m, const float* __restrict__ bn1_v,
    const float* __restrict__ prelu1)
{
    __shared__ float s_w[16 * 64 * 9];          // 36864 B
    __shared__ float s_in[8][18][18];           // 10368 B
    const int t  = threadIdx.x;
    const int b  = blockIdx.z;
    const int x0 = blockIdx.x * 16, y0 = blockIdx.y * 16;

    for (int idx = t; idx < 16 * 64 * 9; idx += 256) s_w[idx] = en_w[idx];

    const int oc = t & 15, p = t >> 4;
    const int py = (p >> 2) * 4, px = (p & 3) * 4;

    float acc[16];
#pragma unroll
    for (int i = 0; i < 16; i++) acc[i] = 0.f;

    const float* emb = em + (size_t)b * 64 * 128 * 128;

    for (int ic0 = 0; ic0 < 64; ic0 += 8) {
        __syncthreads();
        for (int idx = t; idx < 8 * 18 * 18; idx += 256) {
            int ic = idx / 324; int rem = idx % 324;
            int yy = rem / 18, xx = rem % 18;
            int gy = y0 - 1 + yy, gx = x0 - 1 + xx;
            float v = 0.f;
            if (gy >= 0 && gy < 128 && gx >= 0 && gx < 128)
                v = emb[(size_t)(ic0 + ic) * 16384 + gy * 128 + gx];
            s_in[ic][yy][xx] = v;
        }
        __syncthreads();
        for (int ic = 0; ic < 8; ic++) {
            float w[9];
#pragma unroll
            for (int k = 0; k < 9; k++) w[k] = s_w[oc * 576 + (ic0 + ic) * 9 + k];
            float r[36];
#pragma unroll
            for (int yy = 0; yy < 6; yy++)
#pragma unroll
                for (int xx = 0; xx < 6; xx++)
                    r[yy * 6 + xx] = s_in[ic][py + yy][px + xx];
#pragma unroll
            for (int oy = 0; oy < 4; oy++)
#pragma unroll
                for (int ox = 0; ox < 4; ox++) {
                    float a = acc[oy * 4 + ox];
#pragma unroll
                    for (int ky = 0; ky < 3; ky++)
#pragma unroll
                        for (int kx = 0; kx < 3; kx++)
                            a = fmaf(r[(oy + ky) * 6 + (ox + kx)], w[ky * 3 + kx], a);
                    acc[oy * 4 + ox] = a;
                }
        }
    }

    const float bias  = en_b[oc];
    const float scale = bn1_g[oc] * rsqrtf(bn1_v[oc] + EPS);
    const float mu    = bn1_m[oc];
    const float bb    = bn1_b[oc];
    const float a1    = prelu1[0];
    float* outp = g_x + (size_t)(b * 16 + oc) * 16384;
#pragma unroll
    for (int oy = 0; oy < 4; oy++)
#pragma unroll
        for (int ox = 0; ox < 4; ox++) {
            float y = (acc[oy * 4 + ox] + bias - mu) * scale + bb;
            y = (y >= 0.f) ? y : a1 * y;
            outp[(y0 + py + oy) * 128 + (x0 + px + ox)] = y;
        }
}

// ============================================================================
// Kernel 2: maxpool3s2p1 + depthwise 1x1  ||  de 1x1 (128->32)  -> f (48ch)
//           then Q/K/V 1x1 projections (48->128 each)
// grid (64 rows, 4 batch), 256 threads. Dynamic smem = 102400 B.
// ============================================================================
__global__ __launch_bounds__(256) void qkv_kernel(
    const float* __restrict__ dm,
    const float* __restrict__ dw_w, const float* __restrict__ dw_b,
    const float* __restrict__ de_w, const float* __restrict__ de_b,
    const float* __restrict__ q_w,  const float* __restrict__ q_b,
    const float* __restrict__ k_w,  const float* __restrict__ k_b,
    const float* __restrict__ v_w,  const float* __restrict__ v_b)
{
    extern __shared__ float sm2[];
    float* f     = sm2;                 // 48*64
    float* s_dew = sm2 + 3072;          // 32*128
    float* s_qw  = sm2 + 3072 + 4096;   // 128*48
    float* s_kw  = s_qw + 6144;
    float* s_vw  = s_kw + 6144;

    const int t = threadIdx.x;
    const int y = blockIdx.x, b = blockIdx.y;

    for (int idx = t; idx < 4096; idx += 256) s_dew[idx] = de_w[idx];
    for (int idx = t; idx < 6144; idx += 256) {
        s_qw[idx] = q_w[idx]; s_kw[idx] = k_w[idx]; s_vw[idx] = v_w[idx];
    }

    // Phase A1: maxpool(3,3,s2,p1) + depthwise 1x1 -> f[0:16]
    for (int idx = t; idx < 1024; idx += 256) {
        int c = idx >> 6, x = idx & 63;
        const float* xp = g_x + (size_t)(b * 16 + c) * 16384;
        float mval = -1e30f;
        int ys = 2 * y - 1, xs = 2 * x - 1;
#pragma unroll
        for (int dy = 0; dy < 3; dy++) {
            int yy = ys + dy;
            if (yy < 0 || yy > 127) continue;
#pragma unroll
            for (int dx = 0; dx < 3; dx++) {
                int xx = xs + dx;
                if (xx < 0 || xx > 127) continue;
                mval = fmaxf(mval, xp[yy * 128 + xx]);
            }
        }
        f[c * 64 + x] = mval * dw_w[c] + dw_b[c];
    }
    __syncthreads();

    // Phase A2: de 1x1 conv (128 -> 32) -> f[16:48]
    {
        int x = t & 63, g = t >> 6;     // g in 0..3, 8 oc each
        float acc8[8];
#pragma unroll
        for (int k = 0; k < 8; k++) acc8[k] = 0.f;
        const float* dmb = dm + (size_t)b * 128 * 4096 + y * 64 + x;
        for (int ic = 0; ic < 128; ic++) {
            float d = dmb[(size_t)ic * 4096];
#pragma unroll
            for (int k = 0; k < 8; k++)
                acc8[k] = fmaf(d, s_dew[(g * 8 + k) * 128 + ic], acc8[k]);
        }
#pragma unroll
        for (int k = 0; k < 8; k++)
            f[(16 + g * 8 + k) * 64 + x] = acc8[k] + de_b[g * 8 + k];
    }
    __syncthreads();

    // Phase B: QKV projections (48 -> 128 each)
    {
        int x = t & 63, g = t >> 6;     // g in 0..3, 32 a-channels each
        float fr[48];
#pragma unroll
        for (int c = 0; c < 48; c++) fr[c] = f[c * 64 + x];
        const int n = y * 64 + x;
        const size_t base = (size_t)b * 128 * 4096 + n;
        for (int a = g * 32; a < g * 32 + 32; a++) {
            float aq = q_b[a], ak = k_b[a], av = v_b[a];
#pragma unroll
            for (int c = 0; c < 48; c++) {
                float fc = fr[c];
                aq = fmaf(s_qw[a * 48 + c], fc, aq);
                ak = fmaf(s_kw[a * 48 + c], fc, ak);
                av = fmaf(s_vw[a * 48 + c], fc, av);
            }
            g_q[base + (size_t)a * 4096] = aq;
            g_k[base + (size_t)a * 4096] = ak;
            g_v[base + (size_t)a * 4096] = av;
        }
    }
}

// ============================================================================
// Kernel 3: flash-style sigmoid attention + p_v + bottleneck 1x1 + BN + PReLU
// grid (64 i-tiles, 4 batch), 256 threads. Dynamic smem = 115712 B.
// Per block: i-tile of 64 queries; stream 64 j-tiles of 64 keys each.
//   GEMM1: S[64i][64j] = Q^T K   (thread: 4j x 4i, c-loop 128)
//   sigmoid, store S [j][i] padded stride 68
//   GEMM2: acc[128c][64i] += V * S (thread: 8c x 4i, j-loop 64)
// Epilogue: ov = acc + V*p ; out = prelu(bn(bt_w @ ov + bt_b))
// ============================================================================
__global__ __launch_bounds__(256) void attn_kernel(
    const float* __restrict__ pmask,
    const float* __restrict__ bt_w, const float* __restrict__ bt_b,
    const float* __restrict__ bn2_g, const float* __restrict__ bn2_b,
    const float* __restrict__ bn2_m, const float* __restrict__ bn2_v,
    const float* __restrict__ prelu2,
    float* __restrict__ out)
{
    extern __shared__ float sm3[];
    float* Qs = sm3;            // [128][64]
    float* Ks = sm3 + 8192;     // [128][64]
    float* Vs = sm3 + 16384;    // [128][64]
    float* Ss = sm3 + 24576;    // [64][68] padded

    const int t = threadIdx.x;
    const int b = blockIdx.y;
    const int ibase = blockIdx.x * 64;

    const float* Qg = g_q + (size_t)b * 128 * 4096 + ibase;
    const float* Kg = g_k + (size_t)b * 128 * 4096;
    const float* Vg = g_v + (size_t)b * 128 * 4096;

    for (int idx = t; idx < 8192; idx += 256) {
        int c = idx >> 6, i = idx & 63;
        Qs[idx] = Qg[(size_t)c * 4096 + i];
    }

    const int ig = t & 15;          // i-group: i0 = ig*4 (shared by both GEMMs)
    const int jg = t >> 4;          // GEMM1 j-group: j0 = jg*4
    const int cg = t >> 4;          // GEMM2 c-group: c0 = cg*8

    float acc[8][4];
#pragma unroll
    for (int a = 0; a < 8; a++)
#pragma unroll
        for (int i2 = 0; i2 < 4; i2++) acc[a][i2] = 0.f;

    for (int jt = 0; jt < 64; jt++) {
        __syncthreads();
        const int jb = jt * 64;
        for (int idx = t; idx < 8192; idx += 256) {
            int c = idx >> 6, j = idx & 63;
            Ks[idx] = Kg[(size_t)c * 4096 + jb + j];
            Vs[idx] = Vg[(size_t)c * 4096 + jb + j];
        }
        __syncthreads();

        // ---- GEMM1: S = Q^T K ----
        float s[4][4];
#pragma unroll
        for (int a = 0; a < 4; a++)
#pragma unroll
            for (int i2 = 0; i2 < 4; i2++) s[a][i2] = 0.f;

#pragma unroll 4
        for (int c = 0; c < 128; c++) {
            float4 q4 = *(const float4*)(Qs + c * 64 + ig * 4);
            float4 k4 = *(const float4*)(Ks + c * 64 + jg * 4);
            float qv[4] = {q4.x, q4.y, q4.z, q4.w};
            float kv[4] = {k4.x, k4.y, k4.z, k4.w};
#pragma unroll
            for (int jj = 0; jj < 4; jj++)
#pragma unroll
                for (int ii = 0; ii < 4; ii++)
                    s[jj][ii] = fmaf(kv[jj], qv[ii], s[jj][ii]);
        }

        // sigmoid + store S[j][i]
#pragma unroll
        for (int jj = 0; jj < 4; jj++) {
            float4 o;
            o.x = 1.f / (1.f + __expf(-s[jj][0]));
            o.y = 1.f / (1.f + __expf(-s[jj][1]));
            o.z = 1.f / (1.f + __expf(-s[jj][2]));
            o.w = 1.f / (1.f + __expf(-s[jj][3]));
            *(float4*)(Ss + (jg * 4 + jj) * 68 + ig * 4) = o;
        }
        __syncthreads();

        // ---- GEMM2: acc += V * S^T ----
#pragma unroll 2
        for (int j = 0; j < 64; j += 4) {
            float sv[4][4];
#pragma unroll
            for (int jj = 0; jj < 4; jj++) {
                float4 x4 = *(const float4*)(Ss + (j + jj) * 68 + ig * 4);
                sv[jj][0] = x4.x; sv[jj][1] = x4.y; sv[jj][2] = x4.z; sv[jj][3] = x4.w;
            }
#pragma unroll
            for (int cc = 0; cc < 8; cc++) {
                float4 v4 = *(const float4*)(Vs + (cg * 8 + cc) * 64 + j);
                float vv[4] = {v4.x, v4.y, v4.z, v4.w};
#pragma unroll
                for (int jj = 0; jj < 4; jj++)
#pragma unroll
                    for (int ii = 0; ii < 4; ii++)
                        acc[cc][ii] = fmaf(vv[jj], sv[jj][ii], acc[cc][ii]);
            }
        }
    }

    // ---- Epilogue ----
    __syncthreads();                  // all GEMM1/GEMM2 done; Qs/Ks reusable

    float4 p4 = *(const float4*)(pmask + b * 4096 + ibase + ig * 4);
    float pp[4] = {p4.x, p4.y, p4.z, p4.w};

    // ov = acc + V * p  -> Qs[c][i]
#pragma unroll
    for (int cc = 0; cc < 8; cc++) {
        int c = cg * 8 + cc;
        float4 v4 = *(const float4*)(Vg + (size_t)c * 4096 + ibase + ig * 4);
        float vv[4] = {v4.x, v4.y, v4.z, v4.w};
        float4 o;
        o.x = acc[cc][0] + vv[0] * pp[0];
        o.y = acc[cc][1] + vv[1] * pp[1];
        o.z = acc[cc][2] + vv[2] * pp[2];
        o.w = acc[cc][3] + vv[3] * pp[3];
        *(float4*)(Qs + c * 64 + ig * 4) = o;
    }
    for (int idx = t; idx < 8192; idx += 256) Ks[idx] = bt_w[idx];
    __syncthreads();

    // bottleneck: out[o][i] = prelu(bn(sum_c bt_w[o][c] * ov[c][i] + bt_b[o]))
    const int og = t >> 4;            // o0 = og*4
    float o4[4][4];
#pragma unroll
    for (int a = 0; a < 4; a++)
#pragma unroll
        for (int i2 = 0; i2 < 4; i2++) o4[a][i2] = 0.f;

#pragma unroll 4
    for (int c = 0; c < 128; c++) {
        float4 v4 = *(const float4*)(Qs + c * 64 + ig * 4);
        float ov[4] = {v4.x, v4.y, v4.z, v4.w};
#pragma unroll
        for (int oo = 0; oo < 4; oo++) {
            float w = Ks[(og * 4 + oo) * 128 + c];
#pragma unroll
            for (int ii = 0; ii < 4; ii++)
                o4[oo][ii] = fmaf(w, ov[ii], o4[oo][ii]);
        }
    }

    const float a2 = prelu2[0];
#pragma unroll
    for (int oo = 0; oo < 4; oo++) {
        int o = og * 4 + oo;
        float scale = bn2_g[o] * rsqrtf(bn2_v[o] + EPS);
        float sh    = bt_b[o] - bn2_m[o];
        float bb    = bn2_b[o];
        float r[4];
#pragma unroll
        for (int ii = 0; ii < 4; ii++) {
            float y = (o4[oo][ii] + sh) * scale + bb;
            r[ii] = (y >= 0.f) ? y : a2 * y;
        }
        float4 w4; w4.x = r[0]; w4.y = r[1]; w4.z = r[2]; w4.w = r[3];
        *(float4*)(out + (size_t)(b * 64 + o) * 4096 + ibase + ig * 4) = w4;
    }
}

// ============================================================================
extern "C" void kernel_launch(void* const* d_in, const int* in_sizes, int n_in,
                              void* d_out, int out_size)
{
    const float* em     = (const float*)d_in[0];
    const float* dm     = (const float*)d_in[1];
    const float* p      = (const float*)d_in[2];
    const float* en_w   = (const float*)d_in[3];
    const float* en_b   = (const float*)d_in[4];
    const float* bn1_g  = (const float*)d_in[5];
    const float* bn1_b  = (const float*)d_in[6];
    const float* bn1_m  = (const float*)d_in[7];
    const float* bn1_v  = (const float*)d_in[8];
    const float* prelu1 = (const float*)d_in[9];
    const float* dw_w   = (const float*)d_in[10];
    const float* dw_b   = (const float*)d_in[11];
    const float* de_w   = (const float*)d_in[12];
    const float* de_b   = (const float*)d_in[13];
    const float* q_w    = (const float*)d_in[14];
    const float* q_b    = (const float*)d_in[15];
    const float* k_w    = (const float*)d_in[16];
    const float* k_b    = (const float*)d_in[17];
    const float* v_w    = (const float*)d_in[18];
    const float* v_b    = (const float*)d_in[19];
    const float* bt_w   = (const float*)d_in[20];
    const float* bt_b   = (const float*)d_in[21];
    const float* bn2_g  = (const float*)d_in[22];
    const float* bn2_b  = (const float*)d_in[23];
    const float* bn2_m  = (const float*)d_in[24];
    const float* bn2_v  = (const float*)d_in[25];
    const float* prelu2 = (const float*)d_in[26];
    float* out = (float*)d_out;

    const int SMEM2 = 25600 * 4;   // 102400 B
    const int SMEM3 = (24576 + 64 * 68) * 4;  // 115712 B
    cudaFuncSetAttribute(qkv_kernel,  cudaFuncAttributeMaxDynamicSharedMemorySize, SMEM2);
    cudaFuncSetAttribute(attn_kernel, cudaFuncAttributeMaxDynamicSharedMemorySize, SMEM3);

    conv3_kernel<<<dim3(8, 8, 4), 256>>>(em, en_w, en_b, bn1_g, bn1_b, bn1_m, bn1_v, prelu1);
    qkv_kernel<<<dim3(64, 4), 256, SMEM2>>>(dm, dw_w, dw_b, de_w, de_b,
                                            q_w, q_b, k_w, k_b, v_w, v_b);
    attn_kernel<<<dim3(64, 4), 256, SMEM3>>>(p, bt_w, bt_b,
                                             bn2_g, bn2_b, bn2_m, bn2_v, prelu2, out);
}